// round 4
// baseline (speedup 1.0000x reference)
#include <cuda_runtime.h>

// Shapes (fixed by the problem)
#define BB   4
#define LL   2048
#define DD   1024
#define VV   32
#define KK   4096
#define NTOK (BB*LL)     // 8192 tokens
#define TPB  16          // tokens per block
#define TILE 128         // codes per smem tile
#define NTILE (KK/TILE)  // 32 tiles

// Scratch (static device globals — no allocation)
__device__ float g_embn[KK*VV];   // normalized codebook
__device__ float g_ne2[KK];       // sum(emb_n^2) per code
__device__ float g_wpiT[VV*DD];   // Wpi transposed: [v][d]

typedef unsigned long long ull;

__device__ __forceinline__ ull fma2(ull a, ull b, ull c){
    ull d;
    asm("fma.rn.f32x2 %0, %1, %2, %3;" : "=l"(d) : "l"(a), "l"(b), "l"(c));
    return d;
}
__device__ __forceinline__ ull pack2(float x, float y){
    ull r;
    asm("mov.b64 %0, {%1, %2};" : "=l"(r) : "f"(x), "f"(y));
    return r;
}
__device__ __forceinline__ float2 unpack2(ull a){
    float x, y;
    asm("mov.b64 {%0, %1}, %2;" : "=f"(x), "=f"(y) : "l"(a));
    return make_float2(x, y);
}
__device__ __forceinline__ void cp16(void* dst, const void* src){
    unsigned s = (unsigned)__cvta_generic_to_shared(dst);
    asm volatile("cp.async.cg.shared.global [%0], [%1], 16;" :: "r"(s), "l"(src));
}
__device__ __forceinline__ void cp4(void* dst, const void* src){
    unsigned s = (unsigned)__cvta_generic_to_shared(dst);
    asm volatile("cp.async.ca.shared.global [%0], [%1], 4;" :: "r"(s), "l"(src));
}

// ---------------------------------------------------------------------------
// Prep 1: normalize codebook rows, compute ne2 = sum(emb_n^2)
// grid 512, block 256 (warp per row)
// ---------------------------------------------------------------------------
__global__ void prep_emb_kernel(const float* __restrict__ emb){
    int r = blockIdx.x * 8 + (threadIdx.x >> 5);
    int v = threadIdx.x & 31;
    float val = emb[r*VV + v];
    float ss = val * val;
    #pragma unroll
    for(int o=16;o;o>>=1) ss += __shfl_xor_sync(0xffffffffu, ss, o);
    float en = val * rsqrtf(ss);
    g_embn[r*VV + v] = en;
    float s2 = en * en;
    #pragma unroll
    for(int o=16;o;o>>=1) s2 += __shfl_xor_sync(0xffffffffu, s2, o);
    if(v == 0) g_ne2[r] = s2;
}

// ---------------------------------------------------------------------------
// Prep 2: transpose Wpi [D,V] -> WpiT [V,D]; write vq_loss = 0
// grid 128, block 256
// ---------------------------------------------------------------------------
__global__ void prep_wpi_kernel(const float* __restrict__ Wpi,
                                float* __restrict__ out, long long out_size){
    int i = blockIdx.x * 256 + threadIdx.x;
    if(i < VV*DD){
        int d = i >> 5, v = i & 31;
        g_wpiT[v*DD + d] = Wpi[i];
    }
    if(i == 0){
        long long qn = (long long)NTOK * DD;
        if(out_size >= qn + NTOK + 1) out[qn + NTOK] = 0.0f;  // vq_loss
    }
}

// ---------------------------------------------------------------------------
// Main fused kernel: 16 tokens per block (2 per warp, register-resident)
// ---------------------------------------------------------------------------
__global__ void __launch_bounds__(256, 1)
vq_main_kernel(const float* __restrict__ h,
               const float* __restrict__ attn_mask,
               const float* __restrict__ Wp,
               const float* __restrict__ bp,
               const float* __restrict__ bpi,
               float* __restrict__ out, long long out_size)
{
    // row pad 36 floats (144B): LDS.128 conflict-free for lane-strided rows
    __shared__ __align__(16) float s_e[2][TILE*36];   // 36.9 KB, also reused as reduce scratch
    __shared__ __align__(16) float s_ne2[2][TILE];
    __shared__ __align__(16) float s_hp[TPB*32];      // 2*normalized hp
    __shared__ __align__(16) float s_q[TPB*32];       // masked soft-quantized vectors

    const int tid  = threadIdx.x;
    const int w    = tid >> 5;
    const int lane = tid & 31;
    const int tokA = blockIdx.x * TPB + 2*w;
    const int tokB = tokA + 1;

    // ---- kick off tile 0 load (overlaps with phase 1) ----
    {
        const float* src = g_embn;  // tile 0
        #pragma unroll
        for(int r=0;r<4;r++){
            int idx = tid + 256*r;            // 0..1023
            int c = idx >> 3, u = idx & 7;
            cp16(&s_e[0][c*36 + u*4], src + c*VV + u*4);
        }
        if(tid < TILE) cp4(&s_ne2[0][tid], g_ne2 + tid);
        asm volatile("cp.async.commit_group;");
    }

    // ---- phase 1: hp = h @ Wp^T + bp, L2-normalize, fold 2x for scores ----
    {
        const float4* hA = (const float4*)(h + (long long)tokA * DD);
        const float4* hB = (const float4*)(h + (long long)tokB * DD);
        const float4* wr = (const float4*)(Wp + lane * DD);
        float bpl = __ldg(bp + lane);
        float dA = bpl, dB = bpl;
        #pragma unroll 8
        for(int i=0;i<DD/4;i++){
            float4 wv = __ldg(wr + i);
            float4 a  = __ldg(hA + i);
            float4 b  = __ldg(hB + i);
            dA += wv.x*a.x + wv.y*a.y + wv.z*a.z + wv.w*a.w;
            dB += wv.x*b.x + wv.y*b.y + wv.z*b.z + wv.w*b.w;
        }
        float ssA = dA*dA, ssB = dB*dB;
        #pragma unroll
        for(int o=16;o;o>>=1){
            ssA += __shfl_xor_sync(0xffffffffu, ssA, o);
            ssB += __shfl_xor_sync(0xffffffffu, ssB, o);
        }
        // store 2*normalized hp so dot gives 2*s directly
        s_hp[(2*w  )*32 + lane] = dA * (2.0f * rsqrtf(ssA));
        s_hp[(2*w+1)*32 + lane] = dB * (2.0f * rsqrtf(ssB));
        __syncwarp();
    }

    // load hp (as packed f32x2) to registers
    ull hpA[16], hpB[16];
    {
        const ulonglong2* pa = (const ulonglong2*)&s_hp[(2*w  )*32];
        const ulonglong2* pb = (const ulonglong2*)&s_hp[(2*w+1)*32];
        #pragma unroll
        for(int j=0;j<8;j++){
            ulonglong2 x = pa[j]; hpA[2*j] = x.x; hpA[2*j+1] = x.y;
            ulonglong2 y = pb[j]; hpB[2*j] = y.x; hpB[2*j+1] = y.y;
        }
    }

    // ---- main loop: online softmax over K with fixed shift ----
    ull accA[16], accB[16];
    #pragma unroll
    for(int u=0;u<16;u++){ accA[u]=0ull; accB[u]=0ull; }
    float lA = 0.f, lB = 0.f;
    float bestA = -1e30f, bestB = -1e30f;
    int   idxA = 0, idxB = 0;

    for(int t=0;t<NTILE;t++){
        const int buf = t & 1;
        if(t + 1 < NTILE){
            const float* src = g_embn + (t+1)*TILE*VV;
            #pragma unroll
            for(int r=0;r<4;r++){
                int idx = tid + 256*r;
                int c = idx >> 3, u = idx & 7;
                cp16(&s_e[buf^1][c*36 + u*4], src + c*VV + u*4);
            }
            if(tid < TILE) cp4(&s_ne2[buf^1][tid], g_ne2 + (t+1)*TILE + tid);
        }
        asm volatile("cp.async.commit_group;");
        asm volatile("cp.async.wait_group 1;");
        __syncthreads();

        #pragma unroll 1
        for(int j=0;j<4;j++){
            const int c = lane + 32*j;
            const ulonglong2* er = (const ulonglong2*)&s_e[buf][c*36];
            ull e[16];
            #pragma unroll
            for(int u=0;u<8;u++){ ulonglong2 x = er[u]; e[2*u] = x.x; e[2*u+1] = x.y; }

            ull sA = 0ull, sB = 0ull;
            #pragma unroll
            for(int u=0;u<16;u++){ sA = fma2(hpA[u], e[u], sA); sB = fma2(hpB[u], e[u], sB); }
            float2 fa = unpack2(sA), fb = unpack2(sB);
            float ne2 = s_ne2[buf][c];
            float scA = (fa.x + fa.y) - ne2;       // = 2*s - ne2
            float scB = (fb.x + fb.y) - ne2;
            int   code = t*TILE + c;
            if(scA > bestA){ bestA = scA; idxA = code; }
            if(scB > bestB){ bestB = scB; idxB = code; }
            // scores bounded <= ~1.0003 -> fixed shift, no overflow/underflow
            float pA = __expf(scA - 1.0f);
            float pB = __expf(scB - 1.0f);
            lA += pA; lB += pB;
            ull ppA = pack2(pA, pA), ppB = pack2(pB, pB);
            #pragma unroll
            for(int u=0;u<16;u++){
                accA[u] = fma2(ppA, e[u], accA[u]);
                accB[u] = fma2(ppB, e[u], accB[u]);
            }
        }
        __syncthreads();   // before overwriting this buffer next iteration
    }

    // ---- cross-lane reduction (per-warp private scratch, reuse s_e) ----
    const long long qn = (long long)NTOK * DD;
    float* red  = ((float*)s_e) + w * 1088;           // 32 lanes * 34 floats (pad 2)
    ull*   redu = (ull*)red;
    float mkA = (attn_mask[tokA] == 1.0f) ? 1.0f : 0.0f;
    float mkB = (attn_mask[tokB] == 1.0f) ? 1.0f : 0.0f;

    // token A
    {
        #pragma unroll
        for(int jj=0;jj<16;jj++) redu[lane*17 + jj] = accA[jj];
        __syncwarp();
        float q = 0.f;
        #pragma unroll
        for(int l2=0;l2<32;l2++) q += red[l2*34 + lane];
        float lt = lA;
        #pragma unroll
        for(int o=16;o;o>>=1) lt += __shfl_xor_sync(0xffffffffu, lt, o);
        float bv = bestA; int bi = idxA;
        #pragma unroll
        for(int o=16;o;o>>=1){
            float ov = __shfl_down_sync(0xffffffffu, bv, o);
            int   oi = __shfl_down_sync(0xffffffffu, bi, o);
            if(ov > bv || (ov == bv && oi < bi)){ bv = ov; bi = oi; }
        }
        s_q[(2*w)*32 + lane] = q * (mkA / lt);
        if(lane == 0 && out_size >= qn + NTOK) out[qn + tokA] = mkA * (float)bi;
        __syncwarp();
    }
    // token B
    {
        #pragma unroll
        for(int jj=0;jj<16;jj++) redu[lane*17 + jj] = accB[jj];
        __syncwarp();
        float q = 0.f;
        #pragma unroll
        for(int l2=0;l2<32;l2++) q += red[l2*34 + lane];
        float lt = lB;
        #pragma unroll
        for(int o=16;o;o>>=1) lt += __shfl_xor_sync(0xffffffffu, lt, o);
        float bv = bestB; int bi = idxB;
        #pragma unroll
        for(int o=16;o;o>>=1){
            float ov = __shfl_down_sync(0xffffffffu, bv, o);
            int   oi = __shfl_down_sync(0xffffffffu, bi, o);
            if(ov > bv || (ov == bv && oi < bi)){ bv = ov; bi = oi; }
        }
        s_q[(2*w+1)*32 + lane] = q * (mkB / lt);
        if(lane == 0 && out_size >= qn + NTOK) out[qn + tokB] = mkB * (float)bi;
        __syncwarp();
    }

    // ---- epilogue: out = q @ Wpi^T + bpi (both tokens share WpiT loads) ----
    {
        float4 oA[8], oB[8];
        #pragma unroll
        for(int m=0;m<8;m++){ oA[m] = make_float4(0,0,0,0); oB[m] = make_float4(0,0,0,0); }
        #pragma unroll 2
        for(int v=0;v<32;v++){
            float qa = s_q[(2*w)*32 + v];      // smem broadcast
            float qb = s_q[(2*w+1)*32 + v];
            const float4* wr = (const float4*)(g_wpiT + v*DD);
            #pragma unroll
            for(int m=0;m<8;m++){
                float4 wv = __ldg(wr + m*32 + lane);   // d = 128*m + 4*lane, coalesced
                oA[m].x += qa*wv.x; oA[m].y += qa*wv.y; oA[m].z += qa*wv.z; oA[m].w += qa*wv.w;
                oB[m].x += qb*wv.x; oB[m].y += qb*wv.y; oB[m].z += qb*wv.z; oB[m].w += qb*wv.w;
            }
        }
        float4* outA = (float4*)(out + (long long)tokA * DD);
        float4* outB = (float4*)(out + (long long)tokB * DD);
        const float4* bp4 = (const float4*)bpi;
        #pragma unroll
        for(int m=0;m<8;m++){
            float4 bv = __ldg(bp4 + m*32 + lane);
            float4 a = oA[m]; a.x += bv.x; a.y += bv.y; a.z += bv.z; a.w += bv.w;
            float4 b = oB[m]; b.x += bv.x; b.y += bv.y; b.z += bv.z; b.w += bv.w;
            outA[m*32 + lane] = a;
            outB[m*32 + lane] = b;
        }
    }
}

extern "C" void kernel_launch(void* const* d_in, const int* in_sizes, int n_in,
                              void* d_out, int out_size)
{
    const float* h    = (const float*)d_in[0];   // [B,L,D]
    const float* mask = (const float*)d_in[1];   // [B,L]
    const float* Wp   = (const float*)d_in[2];   // [V,D]
    const float* bp   = (const float*)d_in[3];   // [V]
    const float* Wpi  = (const float*)d_in[4];   // [D,V]
    const float* bpi  = (const float*)d_in[5];   // [D]
    const float* emb  = (const float*)d_in[6];   // [K,V]
    float* out = (float*)d_out;
    long long osz = (long long)out_size;

    prep_emb_kernel<<<KK/8, 256>>>(emb);
    prep_wpi_kernel<<<(VV*DD + 255)/256, 256>>>(Wpi, out, osz);
    vq_main_kernel<<<NTOK/TPB, 256>>>(h, mask, Wp, bp, bpi, out, osz);
}

// round 5
// speedup vs baseline: 1.3669x; 1.3669x over previous
#include <cuda_runtime.h>

// Shapes (fixed by the problem)
#define BB   4
#define LL   2048
#define DD   1024
#define VV   32
#define KK   4096
#define NTOK (BB*LL)     // 8192 tokens
#define TPB  16          // tokens per block
#define TILE 128         // codes per smem tile
#define NTILE (KK/TILE)  // 32 tiles

// Scratch (static device globals — no allocation)
__device__ float g_embn[KK*VV];    // normalized codebook
__device__ float g_ne2[KK];        // sum(emb_n^2) + 1 per code (softmax shift folded)
__device__ float g_wpiT[VV*DD];    // Wpi transposed: [v][d]
__device__ float g_wpT4[DD*VV];    // Wp interleaved: [(d/4)][v][d%4] -> coalesced float4 loads

typedef unsigned long long ull;

__device__ __forceinline__ ull fma2(ull a, ull b, ull c){
    ull d;
    asm("fma.rn.f32x2 %0, %1, %2, %3;" : "=l"(d) : "l"(a), "l"(b), "l"(c));
    return d;
}
__device__ __forceinline__ ull pack2(float x, float y){
    ull r;
    asm("mov.b64 %0, {%1, %2};" : "=l"(r) : "f"(x), "f"(y));
    return r;
}
__device__ __forceinline__ float2 unpack2(ull a){
    float x, y;
    asm("mov.b64 {%0, %1}, %2;" : "=f"(x), "=f"(y) : "l"(a));
    return make_float2(x, y);
}
__device__ __forceinline__ void cp16(void* dst, const void* src){
    unsigned s = (unsigned)__cvta_generic_to_shared(dst);
    asm volatile("cp.async.cg.shared.global [%0], [%1], 16;" :: "r"(s), "l"(src));
}
__device__ __forceinline__ void cp4(void* dst, const void* src){
    unsigned s = (unsigned)__cvta_generic_to_shared(dst);
    asm volatile("cp.async.ca.shared.global [%0], [%1], 4;" :: "r"(s), "l"(src));
}

// ---------------------------------------------------------------------------
// Merged prep kernel:
//   blocks [0,512)   : normalize codebook rows, g_ne2 = sum(emb_n^2) + 1
//   blocks [512,640) : transpose Wpi [D,V] -> WpiT [V,D]; write vq_loss = 0
//   blocks [640,768) : build interleaved WpT4: g_wpT4[(d/4)*128 + v*4 + d%4] = Wp[v][d]
// ---------------------------------------------------------------------------
__global__ void prep_kernel(const float* __restrict__ emb,
                            const float* __restrict__ Wpi,
                            const float* __restrict__ Wp,
                            float* __restrict__ out, long long out_size){
    int b = blockIdx.x;
    if(b < 512){
        int r = b * 8 + (threadIdx.x >> 5);
        int v = threadIdx.x & 31;
        float val = emb[r*VV + v];
        float ss = val * val;
        #pragma unroll
        for(int o=16;o;o>>=1) ss += __shfl_xor_sync(0xffffffffu, ss, o);
        float en = val * rsqrtf(ss);
        g_embn[r*VV + v] = en;
        float s2 = en * en;
        #pragma unroll
        for(int o=16;o;o>>=1) s2 += __shfl_xor_sync(0xffffffffu, s2, o);
        if(v == 0) g_ne2[r] = s2 + 1.0f;   // +1: fixed softmax shift folded in
    } else if(b < 640){
        int i = (b - 512) * 256 + threadIdx.x;   // over D*V
        int d = i >> 5, v = i & 31;              // Wpi[d][v]
        g_wpiT[v*DD + d] = Wpi[i];
        if(i == 0){
            long long qn = (long long)NTOK * DD;
            if(out_size >= qn + NTOK + 1) out[qn + NTOK] = 0.0f;  // vq_loss
        }
    } else {
        int i = (b - 640) * 256 + threadIdx.x;   // over V*D (coalesced Wp read)
        int v = i >> 10, d = i & 1023;           // Wp[v][d]
        g_wpT4[(d >> 2)*128 + v*4 + (d & 3)] = Wp[i];
    }
}

// ---------------------------------------------------------------------------
// Main fused kernel: 16 tokens per block (2 per warp, register-resident)
// ---------------------------------------------------------------------------
__global__ void __launch_bounds__(256, 1)
vq_main_kernel(const float* __restrict__ h,
               const float* __restrict__ attn_mask,
               const float* __restrict__ bp,
               const float* __restrict__ bpi,
               float* __restrict__ out, long long out_size)
{
    // row pad 36 floats (144B): LDS.128 conflict-free for lane-strided rows
    __shared__ __align__(16) float s_e[2][TILE*36];   // 36.9 KB, reused as reduce scratch
    __shared__ __align__(16) float s_ne2[2][TILE];
    __shared__ __align__(16) float s_hp[TPB*32];      // 2*normalized hp
    __shared__ __align__(16) float s_q[TPB*32];       // masked soft-quantized vectors

    const int tid  = threadIdx.x;
    const int w    = tid >> 5;
    const int lane = tid & 31;
    const int tokA = blockIdx.x * TPB + 2*w;
    const int tokB = tokA + 1;

    // ---- kick off tile 0 load (overlaps with phase 1) ----
    {
        const float* src = g_embn;  // tile 0
        #pragma unroll
        for(int r=0;r<4;r++){
            int idx = tid + 256*r;            // 0..1023
            int c = idx >> 3, u = idx & 7;
            cp16(&s_e[0][c*36 + u*4], src + c*VV + u*4);
        }
        if(tid < TILE) cp4(&s_ne2[0][tid], g_ne2 + tid);
        asm volatile("cp.async.commit_group;");
    }

    // ---- phase 1: hp = h @ Wp^T + bp via interleaved WpT4 (coalesced) ----
    {
        const float4* hA4 = (const float4*)(h + (long long)tokA * DD);
        const float4* hB4 = (const float4*)(h + (long long)tokB * DD);
        const float4* wT  = (const float4*)g_wpT4;
        float bpl = __ldg(bp + lane);
        float dA = bpl, dB = bpl;
        #pragma unroll 8
        for(int g=0;g<DD/4;g++){
            float4 wv = __ldg(wT + g*32 + lane);   // lane-consecutive: 4 lines/LDG
            float4 a  = __ldg(hA4 + g);            // warp-uniform broadcast: 1 line
            float4 b  = __ldg(hB4 + g);
            dA += wv.x*a.x + wv.y*a.y + wv.z*a.z + wv.w*a.w;
            dB += wv.x*b.x + wv.y*b.y + wv.z*b.z + wv.w*b.w;
        }
        float ssA = dA*dA, ssB = dB*dB;
        #pragma unroll
        for(int o=16;o;o>>=1){
            ssA += __shfl_xor_sync(0xffffffffu, ssA, o);
            ssB += __shfl_xor_sync(0xffffffffu, ssB, o);
        }
        // store 2*normalized hp so dot gives 2*s directly
        s_hp[(2*w  )*32 + lane] = dA * (2.0f * rsqrtf(ssA));
        s_hp[(2*w+1)*32 + lane] = dB * (2.0f * rsqrtf(ssB));
        __syncwarp();
    }

    // load hp (as packed f32x2) to registers
    ull hpA[16], hpB[16];
    {
        const ulonglong2* pa = (const ulonglong2*)&s_hp[(2*w  )*32];
        const ulonglong2* pb = (const ulonglong2*)&s_hp[(2*w+1)*32];
        #pragma unroll
        for(int j=0;j<8;j++){
            ulonglong2 x = pa[j]; hpA[2*j] = x.x; hpA[2*j+1] = x.y;
            ulonglong2 y = pb[j]; hpB[2*j] = y.x; hpB[2*j+1] = y.y;
        }
    }

    // ---- main loop: online softmax over K with fixed shift (folded into ne2) ----
    ull accA[16], accB[16];
    #pragma unroll
    for(int u=0;u<16;u++){ accA[u]=0ull; accB[u]=0ull; }
    float lA = 0.f, lB = 0.f;
    float bestA = -1e30f, bestB = -1e30f;
    int   idxA = 0, idxB = 0;

    for(int t=0;t<NTILE;t++){
        const int buf = t & 1;
        if(t + 1 < NTILE){
            const float* src = g_embn + (t+1)*TILE*VV;
            #pragma unroll
            for(int r=0;r<4;r++){
                int idx = tid + 256*r;
                int c = idx >> 3, u = idx & 7;
                cp16(&s_e[buf^1][c*36 + u*4], src + c*VV + u*4);
            }
            if(tid < TILE) cp4(&s_ne2[buf^1][tid], g_ne2 + (t+1)*TILE + tid);
        }
        asm volatile("cp.async.commit_group;");
        asm volatile("cp.async.wait_group 1;");
        __syncthreads();

        #pragma unroll 1
        for(int j=0;j<4;j++){
            const int c = lane + 32*j;
            const ulonglong2* er = (const ulonglong2*)&s_e[buf][c*36];
            ull e[16];
            #pragma unroll
            for(int u=0;u<8;u++){ ulonglong2 x = er[u]; e[2*u] = x.x; e[2*u+1] = x.y; }

            ull sA = 0ull, sB = 0ull;
            #pragma unroll
            for(int u=0;u<16;u++){ sA = fma2(hpA[u], e[u], sA); sB = fma2(hpB[u], e[u], sB); }
            float2 fa = unpack2(sA), fb = unpack2(sB);
            float ne2p1 = s_ne2[buf][c];
            float scA = (fa.x + fa.y) - ne2p1;     // = 2*s - ne2 - 1 (shifted score)
            float scB = (fb.x + fb.y) - ne2p1;
            int   code = t*TILE + c;
            if(scA > bestA){ bestA = scA; idxA = code; }
            if(scB > bestB){ bestB = scB; idxB = code; }
            // shifted scores <= ~0.0003 -> no overflow; >= ~-4 -> no underflow
            float pA = __expf(scA);
            float pB = __expf(scB);
            lA += pA; lB += pB;
            ull ppA = pack2(pA, pA), ppB = pack2(pB, pB);
            #pragma unroll
            for(int u=0;u<16;u++){
                accA[u] = fma2(ppA, e[u], accA[u]);
                accB[u] = fma2(ppB, e[u], accB[u]);
            }
        }
        __syncthreads();   // before overwriting this buffer next iteration
    }

    // ---- cross-lane reduction (per-warp private scratch, reuse s_e) ----
    const long long qn = (long long)NTOK * DD;
    float* red  = ((float*)s_e) + w * 1088;           // 32 lanes * 34 floats (pad 2)
    ull*   redu = (ull*)red;
    float mkA = (attn_mask[tokA] == 1.0f) ? 1.0f : 0.0f;
    float mkB = (attn_mask[tokB] == 1.0f) ? 1.0f : 0.0f;

    // token A
    {
        #pragma unroll
        for(int jj=0;jj<16;jj++) redu[lane*17 + jj] = accA[jj];
        __syncwarp();
        float q = 0.f;
        #pragma unroll
        for(int l2=0;l2<32;l2++) q += red[l2*34 + lane];
        float lt = lA;
        #pragma unroll
        for(int o=16;o;o>>=1) lt += __shfl_xor_sync(0xffffffffu, lt, o);
        float bv = bestA; int bi = idxA;
        #pragma unroll
        for(int o=16;o;o>>=1){
            float ov = __shfl_down_sync(0xffffffffu, bv, o);
            int   oi = __shfl_down_sync(0xffffffffu, bi, o);
            if(ov > bv || (ov == bv && oi < bi)){ bv = ov; bi = oi; }
        }
        s_q[(2*w)*32 + lane] = q * (mkA / lt);
        if(lane == 0 && out_size >= qn + NTOK) out[qn + tokA] = mkA * (float)bi;
        __syncwarp();
    }
    // token B
    {
        #pragma unroll
        for(int jj=0;jj<16;jj++) redu[lane*17 + jj] = accB[jj];
        __syncwarp();
        float q = 0.f;
        #pragma unroll
        for(int l2=0;l2<32;l2++) q += red[l2*34 + lane];
        float lt = lB;
        #pragma unroll
        for(int o=16;o;o>>=1) lt += __shfl_xor_sync(0xffffffffu, lt, o);
        float bv = bestB; int bi = idxB;
        #pragma unroll
        for(int o=16;o;o>>=1){
            float ov = __shfl_down_sync(0xffffffffu, bv, o);
            int   oi = __shfl_down_sync(0xffffffffu, bi, o);
            if(ov > bv || (ov == bv && oi < bi)){ bv = ov; bi = oi; }
        }
        s_q[(2*w+1)*32 + lane] = q * (mkB / lt);
        if(lane == 0 && out_size >= qn + NTOK) out[qn + tokB] = mkB * (float)bi;
        __syncwarp();
    }

    // ---- epilogue: out = q @ Wpi^T + bpi (both tokens share WpiT loads) ----
    {
        float4 oA[8], oB[8];
        #pragma unroll
        for(int m=0;m<8;m++){ oA[m] = make_float4(0,0,0,0); oB[m] = make_float4(0,0,0,0); }
        #pragma unroll 2
        for(int v=0;v<32;v++){
            float qa = s_q[(2*w)*32 + v];      // smem broadcast
            float qb = s_q[(2*w+1)*32 + v];
            const float4* wr = (const float4*)(g_wpiT + v*DD);
            #pragma unroll
            for(int m=0;m<8;m++){
                float4 wv = __ldg(wr + m*32 + lane);   // d = 128*m + 4*lane, coalesced
                oA[m].x += qa*wv.x; oA[m].y += qa*wv.y; oA[m].z += qa*wv.z; oA[m].w += qa*wv.w;
                oB[m].x += qb*wv.x; oB[m].y += qb*wv.y; oB[m].z += qb*wv.z; oB[m].w += qb*wv.w;
            }
        }
        float4* outA = (float4*)(out + (long long)tokA * DD);
        float4* outB = (float4*)(out + (long long)tokB * DD);
        const float4* bp4 = (const float4*)bpi;
        #pragma unroll
        for(int m=0;m<8;m++){
            float4 bv = __ldg(bp4 + m*32 + lane);
            float4 a = oA[m]; a.x += bv.x; a.y += bv.y; a.z += bv.z; a.w += bv.w;
            float4 b = oB[m]; b.x += bv.x; b.y += bv.y; b.z += bv.z; b.w += bv.w;
            outA[m*32 + lane] = a;
            outB[m*32 + lane] = b;
        }
    }
}

extern "C" void kernel_launch(void* const* d_in, const int* in_sizes, int n_in,
                              void* d_out, int out_size)
{
    const float* h    = (const float*)d_in[0];   // [B,L,D]
    const float* mask = (const float*)d_in[1];   // [B,L]
    const float* Wp   = (const float*)d_in[2];   // [V,D]
    const float* bp   = (const float*)d_in[3];   // [V]
    const float* Wpi  = (const float*)d_in[4];   // [D,V]
    const float* bpi  = (const float*)d_in[5];   // [D]
    const float* emb  = (const float*)d_in[6];   // [K,V]
    float* out = (float*)d_out;
    long long osz = (long long)out_size;

    prep_kernel<<<768, 256>>>(emb, Wpi, Wp, out, osz);
    vq_main_kernel<<<NTOK/TPB, 256>>>(h, mask, bp, bpi, out, osz);
}